// round 15
// baseline (speedup 1.0000x reference)
#include <cuda_runtime.h>
#include <cuda_fp16.h>
#include <math.h>
#include <stdint.h>

#define B_ 65536
#define F_ 64
#define L_ 32
#define E_ 512

// ---------------- device scratch ----------------
__device__ float g_w[F_];
__device__ float g_wb2[E_];
// A: [b][f*32 + j]  fp16(h*w)                                             (256MB)
__device__ __half g_A[(size_t)B_ * 2048];
// B: [f*32 + r][e]  fp16(W2[f][r][e])                                     (2MB)
__device__ __half g_B[(size_t)F_ * 32 * E_];
// W1 hi/lo: [f][i(32)][hi 32 fp16 | lo 32 fp16]                           (256KB)
__device__ __half g_W1hl[(size_t)F_ * 32 * 64];

// ---------------- asm helpers ----------------
__device__ __forceinline__ uint32_t smem_to_u32(const void* p) {
    uint32_t a;
    asm("{ .reg .u64 t; cvta.to.shared.u64 t, %1; cvt.u32.u64 %0, t; }" : "=r"(a) : "l"(p));
    return a;
}
__device__ __forceinline__ void cp_async16(uint32_t s, const void* g) {
    asm volatile("cp.async.cg.shared.global [%0], [%1], 16;" :: "r"(s), "l"(g));
}
#define CP_COMMIT() asm volatile("cp.async.commit_group;" ::: "memory")
#define CP_WAIT(n)  asm volatile("cp.async.wait_group %0;" :: "n"(n) : "memory")

__device__ __forceinline__ void ldsm_x4(uint32_t* r, uint32_t addr) {
    asm volatile("ldmatrix.sync.aligned.m8n8.x4.shared.b16 {%0,%1,%2,%3}, [%4];"
                 : "=r"(r[0]), "=r"(r[1]), "=r"(r[2]), "=r"(r[3]) : "r"(addr));
}
__device__ __forceinline__ void ldsm_x4_t(uint32_t* r, uint32_t addr) {
    asm volatile("ldmatrix.sync.aligned.m8n8.x4.trans.shared.b16 {%0,%1,%2,%3}, [%4];"
                 : "=r"(r[0]), "=r"(r[1]), "=r"(r[2]), "=r"(r[3]) : "r"(addr));
}
__device__ __forceinline__ void mma_f16(float& d0, float& d1, float& d2, float& d3,
                                        uint32_t a0, uint32_t a1, uint32_t a2, uint32_t a3,
                                        uint32_t b0, uint32_t b1) {
    asm volatile("mma.sync.aligned.m16n8k16.row.col.f32.f16.f16.f32 "
                 "{%0,%1,%2,%3}, {%4,%5,%6,%7}, {%8,%9}, {%0,%1,%2,%3};"
                 : "+f"(d0), "+f"(d1), "+f"(d2), "+f"(d3)
                 : "r"(a0), "r"(a1), "r"(a2), "r"(a3), "r"(b0), "r"(b1));
}
__device__ __forceinline__ uint32_t pack2h(float a, float b) {
    __half2 h = __floats2half2_rn(a, b);
    return *(uint32_t*)&h;
}
__device__ __forceinline__ uint32_t ushalf(__half h) {
    return (uint32_t)__half_as_ushort(h);
}
// Abramowitz-Stegun 7.1.26 erf (|abs err| <= 1.5e-7), branchless GELU
__device__ __forceinline__ float gelu_f(float x) {
    float z = fabsf(x) * 0.70710678118654752f;
    float t = __fdividef(1.0f, fmaf(0.3275911f, z, 1.0f));
    float p = t * fmaf(t, fmaf(t, fmaf(t, fmaf(t, 1.061405429f, -1.453152027f),
                                       1.421413741f), -0.284496736f), 0.254829592f);
    float E = fmaf(-p, __expf(-z * z), 1.0f);
    float er = copysignf(E, x);
    return 0.5f * x * (1.0f + er);
}

// ---------------------------------------------------------------------------
// Prologue: softmax(w_raw) -> g_w (+ output tail), w @ b2 -> g_wb2
// ---------------------------------------------------------------------------
__global__ void prologue_kernel(const float* __restrict__ w_raw,
                                const float* __restrict__ b2,
                                float* __restrict__ d_out, int out_size) {
    __shared__ float sw[F_];
    int tid = threadIdx.x;
    if (tid < F_) sw[tid] = w_raw[tid];
    __syncthreads();
    float m = -INFINITY;
    for (int f = 0; f < F_; f++) m = fmaxf(m, sw[f]);
    float s = 0.f;
    for (int f = 0; f < F_; f++) s += expf(sw[f] - m);
    float inv = 1.f / s;
    __syncthreads();
    if (tid < F_) {
        float wv = expf(sw[tid] - m) * inv;
        sw[tid] = wv;
        g_w[tid] = wv;
        if (out_size >= B_ * E_ + F_) d_out[B_ * E_ + tid] = wv;
    }
    __syncthreads();
    for (int e = tid; e < E_; e += blockDim.x) {
        float acc = 0.f;
        for (int f = 0; f < F_; f++) acc = fmaf(sw[f], b2[f * E_ + e], acc);
        g_wb2[e] = acc;
    }
}

// ---------------------------------------------------------------------------
// Prep: W2 -> g_B fp16;  W1 -> g_W1hl fp16 hi/lo
// ---------------------------------------------------------------------------
__global__ void prep_w2_kernel(const float* __restrict__ W2) {
    int f = blockIdx.x;
    int e = threadIdx.x;
    const float* src = W2 + (size_t)f * L_ * E_ + e;
    __half* dst = g_B + (size_t)(f * 32) * E_ + e;
    #pragma unroll
    for (int j = 0; j < 32; j++)
        dst[(size_t)j * E_] = __float2half(src[(size_t)j * E_]);
}

__global__ void prep_w1_kernel(const float* __restrict__ W1) {
    int f = blockIdx.x, tid = threadIdx.x;
    int i = tid >> 3;              // 0..31
    int j0 = (tid & 7) * 4;        // 0,4,...,28
    float4 v = *(const float4*)(W1 + f * 1024 + i * 32 + j0);
    __half h0 = __float2half(v.x), h1 = __float2half(v.y);
    __half h2 = __float2half(v.z), h3 = __float2half(v.w);
    __half l0 = __float2half(v.x - __half2float(h0));
    __half l1 = __float2half(v.y - __half2float(h1));
    __half l2 = __float2half(v.z - __half2float(h2));
    __half l3 = __float2half(v.w - __half2float(h3));
    __half* dst = g_W1hl + (size_t)f * 2048 + i * 64;
    *(uint2*)(dst + j0)      = make_uint2(ushalf(h0) | (ushalf(h1) << 16),
                                          ushalf(h2) | (ushalf(h3) << 16));
    *(uint2*)(dst + 32 + j0) = make_uint2(ushalf(l0) | (ushalf(l1) << 16),
                                          ushalf(l2) | (ushalf(l3) << 16));
}

// ---------------------------------------------------------------------------
// Stage 1 (tensor-core): enc(fp16) @ W1(hi/lo fp16) via mma (2-pass) ->
// LN on fragments -> fast GELU -> *w[f] -> g_A fp16.
// ONE sync per f: sEnc double-buffered, W1 triple-buffered.
// grid = 512 (128 rows each), block = 256 (8 warps x 16 rows).
// ---------------------------------------------------------------------------
#define T1_ENC   0                 // 2 x 16KB enc buffers
#define T1_W1    32768             // 3 x 4KB W1 buffers
#define T1_B1    (T1_W1 + 12288)   // 8KB fp32
#define T1_G     (T1_B1 + 8192)
#define T1_BT    (T1_G + 8192)
#define T1_W     (T1_BT + 8192)    // 256B (g_w copy)
#define T1_BYTES (T1_W + 256)      // ~69.2KB

__global__ void __launch_bounds__(256)
stage1_kernel(const float* __restrict__ bf,
              const float* __restrict__ b1,
              const float* __restrict__ gamma,
              const float* __restrict__ beta) {
    extern __shared__ char smem[];
    const uint32_t sb = smem_to_u32(smem);
    float* sB1f = (float*)(smem + T1_B1);
    float* sGf  = (float*)(smem + T1_G);
    float* sBtf = (float*)(smem + T1_BT);
    float* sWf  = (float*)(smem + T1_W);

    const int tid = threadIdx.x;
    const int b0 = blockIdx.x * 128;
    const int lane = tid & 31;
    const int warp = tid >> 5;
    const int wr0 = warp * 16;
    const int lr = lane & 15, lc = lane >> 4;
    const int erow = tid & 127;
    const int ehi = tid >> 7;

    // preload b1/gamma/beta/g_w + W1hl[0]
    {
        const float4* s1 = (const float4*)b1;
        const float4* s2 = (const float4*)gamma;
        const float4* s3 = (const float4*)beta;
        float4* d1 = (float4*)sB1f;
        float4* d2 = (float4*)sGf;
        float4* d3 = (float4*)sBtf;
        #pragma unroll
        for (int i = tid; i < 512; i += 256) {
            d1[i] = __ldg(&s1[i]);
            d2[i] = __ldg(&s2[i]);
            d3[i] = __ldg(&s3[i]);
        }
        if (tid < F_) sWf[tid] = g_w[tid];
        int row = tid >> 3, off = (tid & 7) * 16;
        cp_async16(sb + T1_W1 + row * 128 + (off ^ ((row & 7) << 4)),
                   (const char*)g_W1hl + tid * 16);
        CP_COMMIT();
    }
    __syncthreads();

    #pragma unroll 1
    for (int f = 0; f < F_; f++) {
        // prefetch W1[f+1] into buffer (f+1)%3 (last read in iter f-2;
        // all threads have finished iter f-2 once any thread is here, via
        // the single barrier in iter f-1)
        if (f + 1 < F_) {
            int row = tid >> 3, off = (tid & 7) * 16;
            cp_async16(sb + T1_W1 + ((f + 1) % 3) * 4096 + row * 128 +
                           (off ^ ((row & 7) << 4)),
                       (const char*)g_W1hl + (size_t)(f + 1) * 4096 + tid * 16);
        }
        CP_COMMIT();

        // ---- enc into buffer f&1: 1 sincosf + 7 exact-phase doublings ----
        {
            float x = __ldg(&bf[(size_t)(b0 + erow) * F_ + f]);
            float anchor = ehi ? (0.1f * 256.0f) : 0.1f;
            float s, c;
            sincosf(anchor * x, &s, &c);
            float sn[8], cs[8];
            sn[0] = s; cs[0] = c;
            #pragma unroll
            for (int k = 1; k < 8; k++) {
                float s2 = 2.f * s * c;
                float c2 = fmaf(-2.f * s, s, 1.f);
                s = s2; c = c2;
                sn[k] = s; cs[k] = c;
            }
            uint32_t shi[4], chi[4];
            #pragma unroll
            for (int k = 0; k < 4; k++) {
                shi[k] = pack2h(sn[2 * k], sn[2 * k + 1]);
                chi[k] = pack2h(cs[2 * k], cs[2 * k + 1]);
            }
            char* base = smem + T1_ENC + (f & 1) * 16384 + erow * 128;
            int swx = (erow & 7) << 4;
            *(uint4*)(base + ((ehi * 16 +  0) ^ swx)) = make_uint4(shi[0], shi[1], shi[2], shi[3]);
            *(uint4*)(base + ((ehi * 16 + 32) ^ swx)) = make_uint4(chi[0], chi[1], chi[2], chi[3]);
        }
        CP_WAIT(1);         // W1[f] landed
        __syncthreads();    // the ONLY barrier per iteration

        // ---- h = enc @ W1 via mma (2-pass: Ah.Bh + Ah.Bl) ----
        float d[4][4];
        #pragma unroll
        for (int nf = 0; nf < 4; nf++)
            #pragma unroll
            for (int q = 0; q < 4; q++) d[nf][q] = 0.f;

        const uint32_t aE = sb + T1_ENC + (f & 1) * 16384;
        const uint32_t aW = sb + T1_W1 + (f % 3) * 4096;
        const int arow = wr0 + lr;
        const int aswx = (arow & 7) << 4;
        #pragma unroll
        for (int ks = 0; ks < 2; ks++) {
            uint32_t Ah[4], Bh[2][4], Bl[2][4];
            int acb = (ks * 16 + lc * 8) * 2;
            ldsm_x4(Ah, aE + arow * 128 + (acb ^ aswx));
            int krow = ks * 16 + lr;
            int kswx = (krow & 7) << 4;
            #pragma unroll
            for (int g = 0; g < 2; g++) {
                int cb = (g * 16 + lc * 8) * 2;
                ldsm_x4_t(Bh[g], aW + krow * 128 + (cb ^ kswx));
                ldsm_x4_t(Bl[g], aW + krow * 128 + ((64 + cb) ^ kswx));
            }
            #pragma unroll
            for (int nf = 0; nf < 4; nf++)
                mma_f16(d[nf][0], d[nf][1], d[nf][2], d[nf][3],
                        Ah[0], Ah[1], Ah[2], Ah[3],
                        Bh[nf >> 1][(nf & 1) * 2], Bh[nf >> 1][(nf & 1) * 2 + 1]);
            #pragma unroll
            for (int nf = 0; nf < 4; nf++)
                mma_f16(d[nf][0], d[nf][1], d[nf][2], d[nf][3],
                        Ah[0], Ah[1], Ah[2], Ah[3],
                        Bl[nf >> 1][(nf & 1) * 2], Bl[nf >> 1][(nf & 1) * 2 + 1]);
        }

        // ---- epilogue: +b1, LN (frag row sums), GELU, *w, store fp16 ----
        {
            float wf = sWf[f];
            int cb = (lane & 3) * 2;
            float sa1 = 0.f, sa2 = 0.f, sb1 = 0.f, sb2 = 0.f;
            #pragma unroll
            for (int nf = 0; nf < 4; nf++) {
                float2 bb = *(float2*)&sB1f[f * 32 + nf * 8 + cb];
                d[nf][0] += bb.x; d[nf][1] += bb.y;
                d[nf][2] += bb.x; d[nf][3] += bb.y;
                sa1 += d[nf][0] + d[nf][1];
                sa2 = fmaf(d[nf][0], d[nf][0], fmaf(d[nf][1], d[nf][1], sa2));
                sb1 += d[nf][2] + d[nf][3];
                sb2 = fmaf(d[nf][2], d[nf][2], fmaf(d[nf][3], d[nf][3], sb2));
            }
            sa1 += __shfl_xor_sync(0xffffffffu, sa1, 1);
            sa1 += __shfl_xor_sync(0xffffffffu, sa1, 2);
            sa2 += __shfl_xor_sync(0xffffffffu, sa2, 1);
            sa2 += __shfl_xor_sync(0xffffffffu, sa2, 2);
            sb1 += __shfl_xor_sync(0xffffffffu, sb1, 1);
            sb1 += __shfl_xor_sync(0xffffffffu, sb1, 2);
            sb2 += __shfl_xor_sync(0xffffffffu, sb2, 1);
            sb2 += __shfl_xor_sync(0xffffffffu, sb2, 2);
            float meanA = sa1 * (1.f / 32.f);
            float varA  = sa2 * (1.f / 32.f) - meanA * meanA;
            float rstdA = rsqrtf(varA + 1e-5f);
            float meanB = sb1 * (1.f / 32.f);
            float varB  = sb2 * (1.f / 32.f) - meanB * meanB;
            float rstdB = rsqrtf(varB + 1e-5f);

            uint32_t pA[4], pB[4];
            #pragma unroll
            for (int nf = 0; nf < 4; nf++) {
                float2 gg = *(float2*)&sGf[f * 32 + nf * 8 + cb];
                float2 be = *(float2*)&sBtf[f * 32 + nf * 8 + cb];
                float h0 = fmaf((d[nf][0] - meanA) * rstdA, gg.x, be.x);
                float h1 = fmaf((d[nf][1] - meanA) * rstdA, gg.y, be.y);
                float h2 = fmaf((d[nf][2] - meanB) * rstdB, gg.x, be.x);
                float h3 = fmaf((d[nf][3] - meanB) * rstdB, gg.y, be.y);
                pA[nf] = pack2h(gelu_f(h0) * wf, gelu_f(h1) * wf);
                pB[nf] = pack2h(gelu_f(h2) * wf, gelu_f(h3) * wf);
            }
            size_t rowA = (size_t)(b0 + wr0 + (lane >> 2));
            __half* outA = g_A + rowA * 2048 + f * 32 + cb;
            __half* outB = outA + (size_t)8 * 2048;
            #pragma unroll
            for (int nf = 0; nf < 4; nf++) {
                *(uint32_t*)(outA + nf * 8) = pA[nf];
                *(uint32_t*)(outB + nf * 8) = pB[nf];
            }
        }
        // no trailing sync: sEnc double-buffered, W1 triple-buffered
    }
}

// ---------------------------------------------------------------------------
// Stage 2 GEMM (unchanged from round 14): K=2048, 64/iter, one sync/iter.
// ---------------------------------------------------------------------------
#define NSTAGE 3
#define STAGE_BYTES 32768
#define B_OFF 16384
#define NITER 32

__global__ void __launch_bounds__(256, 2)
gemm_kernel(float* __restrict__ out) {
    extern __shared__ char smem[];
    const uint32_t sb = smem_to_u32(smem);
    const int tid = threadIdx.x, wid = tid >> 5, lane = tid & 31;
    const int wm = wid & 1, wn = wid >> 1;
    const int e0 = blockIdx.x * 128, b0 = blockIdx.y * 128;
    const int lr = lane & 15, lc = lane >> 4;

    float d[4][4][4];
    #pragma unroll
    for (int mi = 0; mi < 4; mi++)
        #pragma unroll
        for (int nf = 0; nf < 4; nf++)
            #pragma unroll
            for (int q = 0; q < 4; q++) d[mi][nf][q] = 0.f;

    auto issue_tile = [&](int it) {
        uint32_t s = sb + (it % NSTAGE) * STAGE_BYTES;
        const char* gA0 = (const char*)(g_A + (size_t)b0 * 2048 + it * 64);
        #pragma unroll
        for (int k = 0; k < 4; k++) {
            int c = tid + k * 256;
            int r = c >> 3, off = (c & 7) * 16;
            cp_async16(s + r * 128 + (off ^ ((r & 7) << 4)),
                       gA0 + (size_t)r * 4096 + off);
        }
        const char* gB0 = (const char*)(g_B + (size_t)(it * 64) * E_ + e0);
        uint32_t sB = s + B_OFF;
        #pragma unroll
        for (int k = 0; k < 4; k++) {
            int c = tid + k * 256;
            int kr = c >> 4, off = (c & 15) * 16;
            cp_async16(sB + kr * 256 + (off ^ ((kr & 7) << 4)),
                       gB0 + (size_t)kr * 1024 + off);
        }
    };

    issue_tile(0); CP_COMMIT();
    issue_tile(1); CP_COMMIT();

    #pragma unroll 1
    for (int it = 0; it < NITER; it++) {
        CP_WAIT(1);
        __syncthreads();
        if (it + 2 < NITER) issue_tile(it + 2);
        CP_COMMIT();

        const uint32_t aA = sb + (it % NSTAGE) * STAGE_BYTES;
        const uint32_t aB = aA + B_OFF;

        #pragma unroll
        for (int ks = 0; ks < 4; ks++) {
            uint32_t Af[4][4], Bf[2][4];
            const int brow = ks * 16 + lr;
            #pragma unroll
            for (int g = 0; g < 2; g++) {
                int colb = (wn * 32 + g * 16 + lc * 8) * 2;
                ldsm_x4_t(Bf[g], aB + brow * 256 + (colb ^ ((brow & 7) << 4)));
            }
            const int acol = (ks * 16 + lc * 8) * 2;
            #pragma unroll
            for (int mi = 0; mi < 4; mi++) {
                int row = wm * 64 + mi * 16 + lr;
                ldsm_x4(Af[mi], aA + row * 128 + (acol ^ ((row & 7) << 4)));
            }
            #pragma unroll
            for (int mi = 0; mi < 4; mi++)
                #pragma unroll
                for (int nf = 0; nf < 4; nf++)
                    mma_f16(d[mi][nf][0], d[mi][nf][1], d[mi][nf][2], d[mi][nf][3],
                            Af[mi][0], Af[mi][1], Af[mi][2], Af[mi][3],
                            Bf[nf >> 1][(nf & 1) * 2], Bf[nf >> 1][(nf & 1) * 2 + 1]);
        }
    }

    #pragma unroll
    for (int mi = 0; mi < 4; mi++) {
        int r0 = b0 + wm * 64 + mi * 16 + (lane >> 2);
        #pragma unroll
        for (int nf = 0; nf < 4; nf++) {
            int col = e0 + wn * 32 + nf * 8 + (lane & 3) * 2;
            float bx = __ldg(&g_wb2[col]), by = __ldg(&g_wb2[col + 1]);
            float2 v0 = make_float2(d[mi][nf][0] + bx, d[mi][nf][1] + by);
            float2 v1 = make_float2(d[mi][nf][2] + bx, d[mi][nf][3] + by);
            *(float2*)(out + (size_t)r0 * E_ + col)       = v0;
            *(float2*)(out + (size_t)(r0 + 8) * E_ + col) = v1;
        }
    }
}

// ---------------------------------------------------------------------------
extern "C" void kernel_launch(void* const* d_in, const int* in_sizes, int n_in,
                              void* d_out, int out_size) {
    const float* bf    = (const float*)d_in[0];   // batch_factors [B,F]
    const float* w_raw = (const float*)d_in[1];   // [F]
    const float* W1    = (const float*)d_in[2];   // [F,L,L]
    const float* b1    = (const float*)d_in[3];   // [F,L]
    const float* gamma = (const float*)d_in[4];   // [F,L]
    const float* beta  = (const float*)d_in[5];   // [F,L]
    const float* W2    = (const float*)d_in[6];   // [F,L,E]
    const float* b2    = (const float*)d_in[7];   // [F,E]
    float* out = (float*)d_out;

    prologue_kernel<<<1, 512>>>(w_raw, b2, out, out_size);
    prep_w2_kernel<<<F_, 512>>>(W2);
    prep_w1_kernel<<<F_, 256>>>(W1);

    cudaFuncSetAttribute(stage1_kernel,
                         cudaFuncAttributeMaxDynamicSharedMemorySize, (int)T1_BYTES);
    stage1_kernel<<<B_ / 128, 256, T1_BYTES>>>(bf, b1, gamma, beta);

    size_t g_smem = NSTAGE * STAGE_BYTES;                    // 96KB
    cudaFuncSetAttribute(gemm_kernel,
                         cudaFuncAttributeMaxDynamicSharedMemorySize, (int)g_smem);
    dim3 grid(E_ / 128, B_ / 128);
    gemm_kernel<<<grid, 256, g_smem>>>(out);
}

// round 16
// speedup vs baseline: 1.5657x; 1.5657x over previous
#include <cuda_runtime.h>
#include <cuda_fp16.h>
#include <math.h>
#include <stdint.h>

#define B_ 65536
#define F_ 64
#define L_ 32
#define E_ 512

// ---------------- device scratch ----------------
__device__ float g_w[F_];
__device__ float g_wb2[E_];
// A: [b][f*32 + j]  fp16(h*w)                                             (256MB)
__device__ __half g_A[(size_t)B_ * 2048];
// B: [f*32 + r][e]  fp16(W2[f][r][e])                                     (2MB)
__device__ __half g_B[(size_t)F_ * 32 * E_];
// W1 hi/lo: [f][i(32)][hi 32 fp16 | lo 32 fp16]                           (256KB)
__device__ __half g_W1hl[(size_t)F_ * 32 * 64];

// ---------------- asm helpers ----------------
__device__ __forceinline__ uint32_t smem_to_u32(const void* p) {
    uint32_t a;
    asm("{ .reg .u64 t; cvta.to.shared.u64 t, %1; cvt.u32.u64 %0, t; }" : "=r"(a) : "l"(p));
    return a;
}
__device__ __forceinline__ void cp_async16(uint32_t s, const void* g) {
    asm volatile("cp.async.cg.shared.global [%0], [%1], 16;" :: "r"(s), "l"(g));
}
#define CP_COMMIT() asm volatile("cp.async.commit_group;" ::: "memory")
#define CP_WAIT(n)  asm volatile("cp.async.wait_group %0;" :: "n"(n) : "memory")

__device__ __forceinline__ void ldsm_x4(uint32_t* r, uint32_t addr) {
    asm volatile("ldmatrix.sync.aligned.m8n8.x4.shared.b16 {%0,%1,%2,%3}, [%4];"
                 : "=r"(r[0]), "=r"(r[1]), "=r"(r[2]), "=r"(r[3]) : "r"(addr));
}
__device__ __forceinline__ void ldsm_x4_t(uint32_t* r, uint32_t addr) {
    asm volatile("ldmatrix.sync.aligned.m8n8.x4.trans.shared.b16 {%0,%1,%2,%3}, [%4];"
                 : "=r"(r[0]), "=r"(r[1]), "=r"(r[2]), "=r"(r[3]) : "r"(addr));
}
__device__ __forceinline__ void mma_f16(float& d0, float& d1, float& d2, float& d3,
                                        uint32_t a0, uint32_t a1, uint32_t a2, uint32_t a3,
                                        uint32_t b0, uint32_t b1) {
    asm volatile("mma.sync.aligned.m16n8k16.row.col.f32.f16.f16.f32 "
                 "{%0,%1,%2,%3}, {%4,%5,%6,%7}, {%8,%9}, {%0,%1,%2,%3};"
                 : "+f"(d0), "+f"(d1), "+f"(d2), "+f"(d3)
                 : "r"(a0), "r"(a1), "r"(a2), "r"(a3), "r"(b0), "r"(b1));
}
__device__ __forceinline__ uint32_t pack2h(float a, float b) {
    __half2 h = __floats2half2_rn(a, b);
    return *(uint32_t*)&h;
}
__device__ __forceinline__ uint32_t ushalf(__half h) {
    return (uint32_t)__half_as_ushort(h);
}
// Abramowitz-Stegun 7.1.26 erf (|abs err| <= 1.5e-7), branchless GELU
__device__ __forceinline__ float gelu_f(float x) {
    float z = fabsf(x) * 0.70710678118654752f;
    float t = __fdividef(1.0f, fmaf(0.3275911f, z, 1.0f));
    float p = t * fmaf(t, fmaf(t, fmaf(t, fmaf(t, 1.061405429f, -1.453152027f),
                                       1.421413741f), -0.284496736f), 0.254829592f);
    float E = fmaf(-p, __expf(-z * z), 1.0f);
    float er = copysignf(E, x);
    return 0.5f * x * (1.0f + er);
}

// ---------------------------------------------------------------------------
// Prologue: softmax(w_raw) -> g_w (+ output tail), w @ b2 -> g_wb2
// ---------------------------------------------------------------------------
__global__ void prologue_kernel(const float* __restrict__ w_raw,
                                const float* __restrict__ b2,
                                float* __restrict__ d_out, int out_size) {
    __shared__ float sw[F_];
    int tid = threadIdx.x;
    if (tid < F_) sw[tid] = w_raw[tid];
    __syncthreads();
    float m = -INFINITY;
    for (int f = 0; f < F_; f++) m = fmaxf(m, sw[f]);
    float s = 0.f;
    for (int f = 0; f < F_; f++) s += expf(sw[f] - m);
    float inv = 1.f / s;
    __syncthreads();
    if (tid < F_) {
        float wv = expf(sw[tid] - m) * inv;
        sw[tid] = wv;
        g_w[tid] = wv;
        if (out_size >= B_ * E_ + F_) d_out[B_ * E_ + tid] = wv;
    }
    __syncthreads();
    for (int e = tid; e < E_; e += blockDim.x) {
        float acc = 0.f;
        for (int f = 0; f < F_; f++) acc = fmaf(sw[f], b2[f * E_ + e], acc);
        g_wb2[e] = acc;
    }
}

// ---------------------------------------------------------------------------
// Prep: W2 -> g_B fp16;  W1 -> g_W1hl fp16 hi/lo
// ---------------------------------------------------------------------------
__global__ void prep_w2_kernel(const float* __restrict__ W2) {
    int f = blockIdx.x;
    int e = threadIdx.x;
    const float* src = W2 + (size_t)f * L_ * E_ + e;
    __half* dst = g_B + (size_t)(f * 32) * E_ + e;
    #pragma unroll
    for (int j = 0; j < 32; j++)
        dst[(size_t)j * E_] = __float2half(src[(size_t)j * E_]);
}

__global__ void prep_w1_kernel(const float* __restrict__ W1) {
    int f = blockIdx.x, tid = threadIdx.x;
    int i = tid >> 3;              // 0..31
    int j0 = (tid & 7) * 4;        // 0,4,...,28
    float4 v = *(const float4*)(W1 + f * 1024 + i * 32 + j0);
    __half h0 = __float2half(v.x), h1 = __float2half(v.y);
    __half h2 = __float2half(v.z), h3 = __float2half(v.w);
    __half l0 = __float2half(v.x - __half2float(h0));
    __half l1 = __float2half(v.y - __half2float(h1));
    __half l2 = __float2half(v.z - __half2float(h2));
    __half l3 = __float2half(v.w - __half2float(h3));
    __half* dst = g_W1hl + (size_t)f * 2048 + i * 64;
    *(uint2*)(dst + j0)      = make_uint2(ushalf(h0) | (ushalf(h1) << 16),
                                          ushalf(h2) | (ushalf(h3) << 16));
    *(uint2*)(dst + 32 + j0) = make_uint2(ushalf(l0) | (ushalf(l1) << 16),
                                          ushalf(l2) | (ushalf(l3) << 16));
}

// ---------------------------------------------------------------------------
// Stage 1 (tensor-core): TWO f's per iteration sharing one enc tile
// (f even: cols 0..63, f odd: cols 64..127 of each 128B row).
// enc fp16 @ W1 hi/lo fp16 via mma (2-pass) -> LN -> GELU -> *w -> g_A.
// 2 syncs per pair = 1 per f; W1 pair-double-buffered (2x8KB).
// smem 56KB -> 4 CTAs/SM. grid = 512, block = 256 (8 warps x 16 rows).
// ---------------------------------------------------------------------------
#define T1_ENC   0                 // 16KB: 128 rows x 128B (two f's per row)
#define T1_W1    16384             // 2 x 8KB W1 pair buffers
#define T1_B1    32768             // 8KB fp32
#define T1_G     (T1_B1 + 8192)
#define T1_BT    (T1_G + 8192)
#define T1_BYTES (T1_BT + 8192)    // 56KB

__global__ void __launch_bounds__(256)
stage1_kernel(const float* __restrict__ bf,
              const float* __restrict__ b1,
              const float* __restrict__ gamma,
              const float* __restrict__ beta) {
    extern __shared__ char smem[];
    const uint32_t sb = smem_to_u32(smem);
    float* sB1f = (float*)(smem + T1_B1);
    float* sGf  = (float*)(smem + T1_G);
    float* sBtf = (float*)(smem + T1_BT);

    const int tid = threadIdx.x;
    const int b0 = blockIdx.x * 128;
    const int lane = tid & 31;
    const int warp = tid >> 5;
    const int wr0 = warp * 16;
    const int lr = lane & 15, lc = lane >> 4;
    const int erow = tid & 127;
    const int ehi = tid >> 7;

    // preload b1/gamma/beta + W1 pair 0 (8KB)
    {
        const float4* s1 = (const float4*)b1;
        const float4* s2 = (const float4*)gamma;
        const float4* s3 = (const float4*)beta;
        float4* d1 = (float4*)sB1f;
        float4* d2 = (float4*)sGf;
        float4* d3 = (float4*)sBtf;
        #pragma unroll
        for (int i = tid; i < 512; i += 256) {
            d1[i] = __ldg(&s1[i]);
            d2[i] = __ldg(&s2[i]);
            d3[i] = __ldg(&s3[i]);
        }
        #pragma unroll
        for (int k = 0; k < 2; k++) {
            int idx = tid + k * 256;               // 0..511
            int row = idx >> 3, off = (idx & 7) * 16;
            cp_async16(sb + T1_W1 + row * 128 + (off ^ ((row & 7) << 4)),
                       (const char*)g_W1hl + idx * 16);
        }
        CP_COMMIT();
    }
    __syncthreads();

    #pragma unroll 1
    for (int p = 0; p < 32; p++) {                 // pair p: f = 2p, 2p+1
        // prefetch W1 pair p+1 into the other buffer
        if (p + 1 < 32) {
            #pragma unroll
            for (int k = 0; k < 2; k++) {
                int idx = tid + k * 256;
                int row = idx >> 3, off = (idx & 7) * 16;
                cp_async16(sb + T1_W1 + ((p + 1) & 1) * 8192 + row * 128 +
                               (off ^ ((row & 7) << 4)),
                           (const char*)g_W1hl + (size_t)(p + 1) * 8192 + idx * 16);
            }
        }
        CP_COMMIT();

        // ---- enc for both f's of the pair ----
        {
            char* base = smem + T1_ENC + erow * 128;
            int swx = (erow & 7) << 4;
            float anchor = ehi ? (0.1f * 256.0f) : 0.1f;
            #pragma unroll
            for (int sub = 0; sub < 2; sub++) {
                int f = 2 * p + sub;
                float x = __ldg(&bf[(size_t)(b0 + erow) * F_ + f]);
                float s, c;
                sincosf(anchor * x, &s, &c);
                float sn[8], cs[8];
                sn[0] = s; cs[0] = c;
                #pragma unroll
                for (int k = 1; k < 8; k++) {
                    float s2 = 2.f * s * c;
                    float c2 = fmaf(-2.f * s, s, 1.f);
                    s = s2; c = c2;
                    sn[k] = s; cs[k] = c;
                }
                uint32_t shi[4], chi[4];
                #pragma unroll
                for (int k = 0; k < 4; k++) {
                    shi[k] = pack2h(sn[2 * k], sn[2 * k + 1]);
                    chi[k] = pack2h(cs[2 * k], cs[2 * k + 1]);
                }
                int cb0 = sub * 64 + ehi * 16;
                *(uint4*)(base + ((cb0 +  0) ^ swx)) = make_uint4(shi[0], shi[1], shi[2], shi[3]);
                *(uint4*)(base + ((cb0 + 32) ^ swx)) = make_uint4(chi[0], chi[1], chi[2], chi[3]);
            }
        }
        CP_WAIT(1);         // W1 pair p landed
        __syncthreads();

        // ---- per f: mma h-GEMM + LN + GELU + store ----
        #pragma unroll
        for (int sub = 0; sub < 2; sub++) {
            const int f = 2 * p + sub;
            float d[4][4];
            #pragma unroll
            for (int nf = 0; nf < 4; nf++)
                #pragma unroll
                for (int q = 0; q < 4; q++) d[nf][q] = 0.f;

            const uint32_t aE = sb + T1_ENC;
            const uint32_t aW = sb + T1_W1 + (p & 1) * 8192 + sub * 4096;
            const int arow = wr0 + lr;
            const int aswx = (arow & 7) << 4;
            #pragma unroll
            for (int ks = 0; ks < 2; ks++) {
                uint32_t Ah[4], Bh[2][4], Bl[2][4];
                int acb = sub * 64 + (ks * 16 + lc * 8) * 2;
                ldsm_x4(Ah, aE + arow * 128 + (acb ^ aswx));
                int krow = ks * 16 + lr;
                int kswx = (krow & 7) << 4;
                #pragma unroll
                for (int g = 0; g < 2; g++) {
                    int cb = (g * 16 + lc * 8) * 2;
                    ldsm_x4_t(Bh[g], aW + krow * 128 + (cb ^ kswx));
                    ldsm_x4_t(Bl[g], aW + krow * 128 + ((64 + cb) ^ kswx));
                }
                #pragma unroll
                for (int nf = 0; nf < 4; nf++)
                    mma_f16(d[nf][0], d[nf][1], d[nf][2], d[nf][3],
                            Ah[0], Ah[1], Ah[2], Ah[3],
                            Bh[nf >> 1][(nf & 1) * 2], Bh[nf >> 1][(nf & 1) * 2 + 1]);
                #pragma unroll
                for (int nf = 0; nf < 4; nf++)
                    mma_f16(d[nf][0], d[nf][1], d[nf][2], d[nf][3],
                            Ah[0], Ah[1], Ah[2], Ah[3],
                            Bl[nf >> 1][(nf & 1) * 2], Bl[nf >> 1][(nf & 1) * 2 + 1]);
            }

            // epilogue: +b1, LN (frag row sums), GELU, *w, store fp16
            {
                float wf = __ldg(&g_w[f]);
                int cb = (lane & 3) * 2;
                float sa1 = 0.f, sa2 = 0.f, sb1 = 0.f, sb2 = 0.f;
                #pragma unroll
                for (int nf = 0; nf < 4; nf++) {
                    float2 bb = *(float2*)&sB1f[f * 32 + nf * 8 + cb];
                    d[nf][0] += bb.x; d[nf][1] += bb.y;
                    d[nf][2] += bb.x; d[nf][3] += bb.y;
                    sa1 += d[nf][0] + d[nf][1];
                    sa2 = fmaf(d[nf][0], d[nf][0], fmaf(d[nf][1], d[nf][1], sa2));
                    sb1 += d[nf][2] + d[nf][3];
                    sb2 = fmaf(d[nf][2], d[nf][2], fmaf(d[nf][3], d[nf][3], sb2));
                }
                sa1 += __shfl_xor_sync(0xffffffffu, sa1, 1);
                sa1 += __shfl_xor_sync(0xffffffffu, sa1, 2);
                sa2 += __shfl_xor_sync(0xffffffffu, sa2, 1);
                sa2 += __shfl_xor_sync(0xffffffffu, sa2, 2);
                sb1 += __shfl_xor_sync(0xffffffffu, sb1, 1);
                sb1 += __shfl_xor_sync(0xffffffffu, sb1, 2);
                sb2 += __shfl_xor_sync(0xffffffffu, sb2, 1);
                sb2 += __shfl_xor_sync(0xffffffffu, sb2, 2);
                float meanA = sa1 * (1.f / 32.f);
                float varA  = sa2 * (1.f / 32.f) - meanA * meanA;
                float rstdA = rsqrtf(varA + 1e-5f);
                float meanB = sb1 * (1.f / 32.f);
                float varB  = sb2 * (1.f / 32.f) - meanB * meanB;
                float rstdB = rsqrtf(varB + 1e-5f);

                uint32_t pA[4], pB[4];
                #pragma unroll
                for (int nf = 0; nf < 4; nf++) {
                    float2 gg = *(float2*)&sGf[f * 32 + nf * 8 + cb];
                    float2 be = *(float2*)&sBtf[f * 32 + nf * 8 + cb];
                    float h0 = fmaf((d[nf][0] - meanA) * rstdA, gg.x, be.x);
                    float h1 = fmaf((d[nf][1] - meanA) * rstdA, gg.y, be.y);
                    float h2 = fmaf((d[nf][2] - meanB) * rstdB, gg.x, be.x);
                    float h3 = fmaf((d[nf][3] - meanB) * rstdB, gg.y, be.y);
                    pA[nf] = pack2h(gelu_f(h0) * wf, gelu_f(h1) * wf);
                    pB[nf] = pack2h(gelu_f(h2) * wf, gelu_f(h3) * wf);
                }
                size_t rowA = (size_t)(b0 + wr0 + (lane >> 2));
                __half* outA = g_A + rowA * 2048 + f * 32 + cb;
                __half* outB = outA + (size_t)8 * 2048;
                #pragma unroll
                for (int nf = 0; nf < 4; nf++) {
                    *(uint32_t*)(outA + nf * 8) = pA[nf];
                    *(uint32_t*)(outB + nf * 8) = pB[nf];
                }
            }
        }
        __syncthreads();   // protect enc tile + W1 buffer before next pair
    }
}

// ---------------------------------------------------------------------------
// Stage 2 GEMM (unchanged from round 14): K=2048, 64/iter, one sync/iter.
// ---------------------------------------------------------------------------
#define NSTAGE 3
#define STAGE_BYTES 32768
#define B_OFF 16384
#define NITER 32

__global__ void __launch_bounds__(256, 2)
gemm_kernel(float* __restrict__ out) {
    extern __shared__ char smem[];
    const uint32_t sb = smem_to_u32(smem);
    const int tid = threadIdx.x, wid = tid >> 5, lane = tid & 31;
    const int wm = wid & 1, wn = wid >> 1;
    const int e0 = blockIdx.x * 128, b0 = blockIdx.y * 128;
    const int lr = lane & 15, lc = lane >> 4;

    float d[4][4][4];
    #pragma unroll
    for (int mi = 0; mi < 4; mi++)
        #pragma unroll
        for (int nf = 0; nf < 4; nf++)
            #pragma unroll
            for (int q = 0; q < 4; q++) d[mi][nf][q] = 0.f;

    auto issue_tile = [&](int it) {
        uint32_t s = sb + (it % NSTAGE) * STAGE_BYTES;
        const char* gA0 = (const char*)(g_A + (size_t)b0 * 2048 + it * 64);
        #pragma unroll
        for (int k = 0; k < 4; k++) {
            int c = tid + k * 256;
            int r = c >> 3, off = (c & 7) * 16;
            cp_async16(s + r * 128 + (off ^ ((r & 7) << 4)),
                       gA0 + (size_t)r * 4096 + off);
        }
        const char* gB0 = (const char*)(g_B + (size_t)(it * 64) * E_ + e0);
        uint32_t sB = s + B_OFF;
        #pragma unroll
        for (int k = 0; k < 4; k++) {
            int c = tid + k * 256;
            int kr = c >> 4, off = (c & 15) * 16;
            cp_async16(sB + kr * 256 + (off ^ ((kr & 7) << 4)),
                       gB0 + (size_t)kr * 1024 + off);
        }
    };

    issue_tile(0); CP_COMMIT();
    issue_tile(1); CP_COMMIT();

    #pragma unroll 1
    for (int it = 0; it < NITER; it++) {
        CP_WAIT(1);
        __syncthreads();
        if (it + 2 < NITER) issue_tile(it + 2);
        CP_COMMIT();

        const uint32_t aA = sb + (it % NSTAGE) * STAGE_BYTES;
        const uint32_t aB = aA + B_OFF;

        #pragma unroll
        for (int ks = 0; ks < 4; ks++) {
            uint32_t Af[4][4], Bf[2][4];
            const int brow = ks * 16 + lr;
            #pragma unroll
            for (int g = 0; g < 2; g++) {
                int colb = (wn * 32 + g * 16 + lc * 8) * 2;
                ldsm_x4_t(Bf[g], aB + brow * 256 + (colb ^ ((brow & 7) << 4)));
            }
            const int acol = (ks * 16 + lc * 8) * 2;
            #pragma unroll
            for (int mi = 0; mi < 4; mi++) {
                int row = wm * 64 + mi * 16 + lr;
                ldsm_x4(Af[mi], aA + row * 128 + (acol ^ ((row & 7) << 4)));
            }
            #pragma unroll
            for (int mi = 0; mi < 4; mi++)
                #pragma unroll
                for (int nf = 0; nf < 4; nf++)
                    mma_f16(d[mi][nf][0], d[mi][nf][1], d[mi][nf][2], d[mi][nf][3],
                            Af[mi][0], Af[mi][1], Af[mi][2], Af[mi][3],
                            Bf[nf >> 1][(nf & 1) * 2], Bf[nf >> 1][(nf & 1) * 2 + 1]);
        }
    }

    #pragma unroll
    for (int mi = 0; mi < 4; mi++) {
        int r0 = b0 + wm * 64 + mi * 16 + (lane >> 2);
        #pragma unroll
        for (int nf = 0; nf < 4; nf++) {
            int col = e0 + wn * 32 + nf * 8 + (lane & 3) * 2;
            float bx = __ldg(&g_wb2[col]), by = __ldg(&g_wb2[col + 1]);
            float2 v0 = make_float2(d[mi][nf][0] + bx, d[mi][nf][1] + by);
            float2 v1 = make_float2(d[mi][nf][2] + bx, d[mi][nf][3] + by);
            *(float2*)(out + (size_t)r0 * E_ + col)       = v0;
            *(float2*)(out + (size_t)(r0 + 8) * E_ + col) = v1;
        }
    }
}

// ---------------------------------------------------------------------------
extern "C" void kernel_launch(void* const* d_in, const int* in_sizes, int n_in,
                              void* d_out, int out_size) {
    const float* bf    = (const float*)d_in[0];   // batch_factors [B,F]
    const float* w_raw = (const float*)d_in[1];   // [F]
    const float* W1    = (const float*)d_in[2];   // [F,L,L]
    const float* b1    = (const float*)d_in[3];   // [F,L]
    const float* gamma = (const float*)d_in[4];   // [F,L]
    const float* beta  = (const float*)d_in[5];   // [F,L]
    const float* W2    = (const float*)d_in[6];   // [F,L,E]
    const float* b2    = (const float*)d_in[7];   // [F,E]
    float* out = (float*)d_out;

    prologue_kernel<<<1, 512>>>(w_raw, b2, out, out_size);
    prep_w2_kernel<<<F_, 512>>>(W2);
    prep_w1_kernel<<<F_, 256>>>(W1);

    cudaFuncSetAttribute(stage1_kernel,
                         cudaFuncAttributeMaxDynamicSharedMemorySize, (int)T1_BYTES);
    stage1_kernel<<<B_ / 128, 256, T1_BYTES>>>(bf, b1, gamma, beta);

    size_t g_smem = NSTAGE * STAGE_BYTES;                    // 96KB
    cudaFuncSetAttribute(gemm_kernel,
                         cudaFuncAttributeMaxDynamicSharedMemorySize, (int)g_smem);
    dim3 grid(E_ / 128, B_ / 128);
    gemm_kernel<<<grid, 256, g_smem>>>(out);
}